// round 1
// baseline (speedup 1.0000x reference)
#include <cuda_runtime.h>

#define BB 64
#define HH 16
#define DD 128
#define S_TOT 4096
#define EE 2048
#define NSPLIT 8
#define CHUNK 512
#define TILE 32

// ---------------- scratch (device globals; no allocation allowed) ----------------
__device__ float g_q[BB][EE];
__device__ float g_kn[BB][DD];
__device__ float g_vn[BB][DD];
__device__ float g_po[BB][NSPLIT][HH][DD];
__device__ float g_pm[BB][NSPLIT][HH];
__device__ float g_pl[BB][NSPLIT][HH];
__device__ float g_attn[BB][EE];

// ---------------- f32x2 packed math helpers (FFMA2: only reachable via PTX) ------
__device__ __forceinline__ unsigned long long ffma2u(unsigned long long a,
                                                     unsigned long long b,
                                                     unsigned long long c) {
    unsigned long long d;
    asm("fma.rn.f32x2 %0, %1, %2, %3;" : "=l"(d) : "l"(a), "l"(b), "l"(c));
    return d;
}
__device__ __forceinline__ unsigned long long fmul2u(unsigned long long a,
                                                     unsigned long long b) {
    unsigned long long d;
    asm("mul.rn.f32x2 %0, %1, %2;" : "=l"(d) : "l"(a), "l"(b));
    return d;
}
__device__ __forceinline__ unsigned long long f2u(float x, float y) {
    unsigned long long u;
    asm("mov.b64 %0, {%1,%2};" : "=l"(u) : "f"(x), "f"(y));
    return u;
}
__device__ __forceinline__ float2 u2f(unsigned long long u) {
    float2 f;
    asm("mov.b64 {%0,%1}, %2;" : "=f"(f.x), "=f"(f.y) : "l"(u));
    return f;
}

// ---------------- generic 32x32-tile GEMM: out[64xN] = X[64x2048] @ W[2048xN] + b -
__device__ __forceinline__ void gemm32(const float* __restrict__ X,
                                       const float* __restrict__ W,
                                       const float* __restrict__ bias,
                                       float* __restrict__ out,
                                       int N, int col0, int row0) {
    __shared__ float Xs[32][32];
    __shared__ float Wt[32][34];  // transposed W tile, padded
    const int tid = threadIdx.x;
    const int cl = tid & 31;
    const int rg = tid >> 5;
    unsigned long long acc[4] = {0ull, 0ull, 0ull, 0ull};

    for (int k0 = 0; k0 < EE; k0 += 32) {
        // X tile: 32 rows x 32 k, 256 float4 loads
        {
            int r = tid >> 3, c4 = (tid & 7) * 4;
            float4 xv = *(const float4*)&X[(size_t)(row0 + r) * EE + k0 + c4];
            *(float4*)&Xs[r][c4] = xv;
        }
        // W tile transposed: Wt[col][k]
        {
            int kk = tid >> 3, c4 = (tid & 7) * 4;
            float4 wv = *(const float4*)&W[(size_t)(k0 + kk) * N + col0 + c4];
            Wt[c4 + 0][kk] = wv.x;
            Wt[c4 + 1][kk] = wv.y;
            Wt[c4 + 2][kk] = wv.z;
            Wt[c4 + 3][kk] = wv.w;
        }
        __syncthreads();
#pragma unroll
        for (int kk = 0; kk < 32; kk += 2) {
            unsigned long long w2 = *(const unsigned long long*)&Wt[cl][kk];
#pragma unroll
            for (int j = 0; j < 4; j++) {
                unsigned long long x2 =
                    *(const unsigned long long*)&Xs[rg * 4 + j][kk];
                acc[j] = ffma2u(x2, w2, acc[j]);
            }
        }
        __syncthreads();
    }
#pragma unroll
    for (int j = 0; j < 4; j++) {
        float2 f = u2f(acc[j]);
        int r = row0 + rg * 4 + j;
        out[(size_t)r * N + col0 + cl] = f.x + f.y + bias[col0 + cl];
    }
}

// ---------------- kernel 1: fused QKV projection --------------------------------
__global__ void __launch_bounds__(256) qkv_kernel(const float* __restrict__ x,
                                                  const float* __restrict__ Wq,
                                                  const float* __restrict__ bq,
                                                  const float* __restrict__ Wk,
                                                  const float* __restrict__ bk,
                                                  const float* __restrict__ Wv,
                                                  const float* __restrict__ bv) {
    int ct = blockIdx.x;
    int row0 = blockIdx.y * 32;
    if (ct < 64) {
        gemm32(x, Wq, bq, &g_q[0][0], EE, ct * 32, row0);
    } else if (ct < 68) {
        gemm32(x, Wk, bk, &g_kn[0][0], DD, (ct - 64) * 32, row0);
    } else {
        gemm32(x, Wv, bv, &g_vn[0][0], DD, (ct - 68) * 32, row0);
    }
}

// ---------------- kernel 2: flash-decode attention over cache chunks ------------
__global__ void __launch_bounds__(256) attn_kernel(const float* __restrict__ kc,
                                                   const float* __restrict__ vc,
                                                   const int* __restrict__ pos) {
    const int c = blockIdx.x;  // split index
    const int b = blockIdx.y;  // batch
    const int tid = threadIdx.x;
    const int w = tid >> 5;
    const int l = tid & 31;

    __shared__ float q_s[HH][DD];       // 8 KB
    __shared__ float4 kQ[32][TILE];     // 16 KB, [dimquad][slot^dimquad]
    __shared__ float v_s[TILE][DD];     // 16 KB
    __shared__ float p_s[TILE][17];     // padded probs [slot][head]
    __shared__ float scl[HH];           // per-tile rescale factors

    // load q for this batch (512 float4)
    {
        const float4* qb = (const float4*)&g_q[b][0];
        ((float4*)q_s)[tid] = qb[tid];
        ((float4*)q_s)[tid + 256] = qb[tid + 256];
    }
    const int p_glob = pos[b];
    const int s0 = c * CHUNK;

    // QK state: warp w owns heads 2w, 2w+1
    const int h0 = 2 * w;
    float m0 = -1e30f, m1 = -1e30f, l0 = 0.f, l1 = 0.f;
    // PV state: warp w owns dims [16w,16w+16); lane -> head l>>1, dim-half l&1
    const int hp = l >> 1;
    const int dbase = 16 * w + (l & 1) * 8;
    unsigned long long o[4] = {0ull, 0ull, 0ull, 0ull};
    const float scale = 0.08838834764831845f;  // 1/sqrt(128)

    for (int t = 0; t < CHUNK / TILE; t++) {
        const int sbase = s0 + t * TILE;
        __syncthreads();  // previous tile fully consumed (and q_s ready, iter 0)

        // load K (transposed + xor-swizzled) and V tiles; global reads coalesced
#pragma unroll
        for (int i = tid; i < TILE * 32; i += 256) {
            int s = i >> 5, dq = i & 31;
            size_t gidx = ((size_t)b * S_TOT + sbase + s) * DD + dq * 4;
            kQ[dq][s ^ dq] = *(const float4*)&kc[gidx];
            *(float4*)&v_s[s][dq * 4] = *(const float4*)&vc[gidx];
        }
        // scattered new token overwrites its slot (never mutate input cache)
        const bool fix = (p_glob >= sbase) && (p_glob < sbase + TILE);
        __syncthreads();
        if (fix) {
            if (tid < 32) {
                int pl = p_glob - sbase;
                kQ[tid][pl ^ tid] = *(const float4*)&g_kn[b][tid * 4];
                *(float4*)&v_s[pl][tid * 4] = *(const float4*)&g_vn[b][tid * 4];
            }
            __syncthreads();
        }

        // ---- QK: lane = slot, 2 heads per warp, f32x2 dot over 128 dims ----
        unsigned long long a0 = 0ull, a1 = 0ull;
#pragma unroll
        for (int dq = 0; dq < 32; dq++) {
            ulonglong2 kv = *(const ulonglong2*)&kQ[dq][l ^ dq];
            ulonglong2 q0 = *(const ulonglong2*)&q_s[h0][dq * 4];
            ulonglong2 q1 = *(const ulonglong2*)&q_s[h0 + 1][dq * 4];
            a0 = ffma2u(kv.x, q0.x, a0);
            a0 = ffma2u(kv.y, q0.y, a0);
            a1 = ffma2u(kv.x, q1.x, a1);
            a1 = ffma2u(kv.y, q1.y, a1);
        }
        float2 f0 = u2f(a0), f1 = u2f(a1);
        float sc0 = (f0.x + f0.y) * scale;
        float sc1 = (f1.x + f1.y) * scale;

        // online softmax update (per head, warp-wide)
        float t0 = sc0, t1 = sc1;
#pragma unroll
        for (int off = 16; off; off >>= 1) {
            t0 = fmaxf(t0, __shfl_xor_sync(0xffffffffu, t0, off));
            t1 = fmaxf(t1, __shfl_xor_sync(0xffffffffu, t1, off));
        }
        float nm0 = fmaxf(m0, t0), nm1 = fmaxf(m1, t1);
        float cr0 = __expf(m0 - nm0), cr1 = __expf(m1 - nm1);
        float p0 = __expf(sc0 - nm0), p1 = __expf(sc1 - nm1);
        float ps0 = p0, ps1 = p1;
#pragma unroll
        for (int off = 16; off; off >>= 1) {
            ps0 += __shfl_xor_sync(0xffffffffu, ps0, off);
            ps1 += __shfl_xor_sync(0xffffffffu, ps1, off);
        }
        l0 = l0 * cr0 + ps0;
        l1 = l1 * cr1 + ps1;
        m0 = nm0;
        m1 = nm1;
        p_s[l][h0] = p0;
        p_s[l][h0 + 1] = p1;
        if (l == 0) {
            scl[h0] = cr0;
            scl[h0 + 1] = cr1;
        }
        __syncthreads();

        // ---- PV: warp owns 16 dims for all heads; V reads are broadcasts ----
        {
            float cr = scl[hp];
            unsigned long long cr2 = f2u(cr, cr);
#pragma unroll
            for (int j = 0; j < 4; j++) o[j] = fmul2u(o[j], cr2);
        }
#pragma unroll
        for (int s = 0; s < TILE; s++) {
            float p = p_s[s][hp];
            unsigned long long p2 = f2u(p, p);
            ulonglong2 va = *(const ulonglong2*)&v_s[s][dbase];
            ulonglong2 vb = *(const ulonglong2*)&v_s[s][dbase + 4];
            o[0] = ffma2u(va.x, p2, o[0]);
            o[1] = ffma2u(va.y, p2, o[1]);
            o[2] = ffma2u(vb.x, p2, o[2]);
            o[3] = ffma2u(vb.y, p2, o[3]);
        }
    }
    __syncthreads();

    // write split partials
    if (l == 0) {
        g_pm[b][c][h0] = m0;
        g_pl[b][c][h0] = l0;
        g_pm[b][c][h0 + 1] = m1;
        g_pl[b][c][h0 + 1] = l1;
    }
    {
        float* op = &g_po[b][c][hp][dbase];
        float2 f;
        f = u2f(o[0]); op[0] = f.x; op[1] = f.y;
        f = u2f(o[1]); op[2] = f.x; op[3] = f.y;
        f = u2f(o[2]); op[4] = f.x; op[5] = f.y;
        f = u2f(o[3]); op[6] = f.x; op[7] = f.y;
    }
}

// ---------------- kernel 3: combine split partials ------------------------------
__global__ void __launch_bounds__(256) combine_kernel() {
    const int b = blockIdx.x;
    const int tid = threadIdx.x;
    __shared__ float wgt[HH][NSPLIT];
    if (tid < HH) {
        float M = -1e30f;
#pragma unroll
        for (int cc = 0; cc < NSPLIT; cc++) M = fmaxf(M, g_pm[b][cc][tid]);
        float e[NSPLIT];
        float den = 0.f;
#pragma unroll
        for (int cc = 0; cc < NSPLIT; cc++) {
            e[cc] = __expf(g_pm[b][cc][tid] - M);
            den += e[cc] * g_pl[b][cc][tid];
        }
        float inv = 1.f / den;
#pragma unroll
        for (int cc = 0; cc < NSPLIT; cc++) wgt[tid][cc] = e[cc] * inv;
    }
    __syncthreads();
    for (int i = tid; i < EE; i += 256) {
        int h = i >> 7, d = i & 127;
        float acc = 0.f;
#pragma unroll
        for (int cc = 0; cc < NSPLIT; cc++) acc += wgt[h][cc] * g_po[b][cc][h][d];
        g_attn[b][i] = acc;
    }
}

// ---------------- kernel 4: output projection -----------------------------------
__global__ void __launch_bounds__(256) oproj_kernel(const float* __restrict__ Wo,
                                                    const float* __restrict__ bo,
                                                    float* __restrict__ out) {
    gemm32(&g_attn[0][0], Wo, bo, out, EE, blockIdx.x * 32, blockIdx.y * 32);
}

// ---------------- launch --------------------------------------------------------
extern "C" void kernel_launch(void* const* d_in, const int* in_sizes, int n_in,
                              void* d_out, int out_size) {
    const float* x  = (const float*)d_in[0];
    const float* kc = (const float*)d_in[1];
    const float* vc = (const float*)d_in[2];
    const int* pos  = (const int*)d_in[3];
    const float* Wq = (const float*)d_in[4];
    const float* bq = (const float*)d_in[5];
    const float* Wk = (const float*)d_in[6];
    const float* bk = (const float*)d_in[7];
    const float* Wv = (const float*)d_in[8];
    const float* bv = (const float*)d_in[9];
    const float* Wo = (const float*)d_in[10];
    const float* bo = (const float*)d_in[11];
    float* out = (float*)d_out;

    qkv_kernel<<<dim3(72, 2), 256>>>(x, Wq, bq, Wk, bk, Wv, bv);
    attn_kernel<<<dim3(NSPLIT, BB), 256>>>(kc, vc, pos);
    combine_kernel<<<BB, 256>>>();
    oproj_kernel<<<dim3(64, 2), 256>>>(Wo, bo, out);
}

// round 2
// speedup vs baseline: 1.3978x; 1.3978x over previous
#include <cuda_runtime.h>

#define BB 64
#define HH 16
#define DD 128
#define S_TOT 4096
#define EE 2048
#define NSPLIT 8
#define CHUNK 512
#define TILE 32
#define KSPLIT 8
#define KCH 256   // 2048 / KSPLIT

// ---------------- scratch (device globals; no allocation allowed) ----------------
__device__ float g_q[BB][EE];
__device__ float g_kn[BB][DD];
__device__ float g_vn[BB][DD];
__device__ float g_po[BB][NSPLIT][HH][DD];
__device__ float g_pm[BB][NSPLIT][HH];
__device__ float g_pl[BB][NSPLIT][HH];
__device__ float g_attn[BB][EE];
__device__ float g_part[KSPLIT][BB][2304];   // qkv partials: 2048 q | 128 k | 128 v
__device__ float g_part2[KSPLIT][BB][EE];    // oproj partials

// ---------------- f32x2 packed math helpers --------------------------------------
__device__ __forceinline__ unsigned long long ffma2u(unsigned long long a,
                                                     unsigned long long b,
                                                     unsigned long long c) {
    unsigned long long d;
    asm("fma.rn.f32x2 %0, %1, %2, %3;" : "=l"(d) : "l"(a), "l"(b), "l"(c));
    return d;
}
__device__ __forceinline__ unsigned long long fmul2u(unsigned long long a,
                                                     unsigned long long b) {
    unsigned long long d;
    asm("mul.rn.f32x2 %0, %1, %2;" : "=l"(d) : "l"(a), "l"(b));
    return d;
}
__device__ __forceinline__ unsigned long long f2u(float x, float y) {
    unsigned long long u;
    asm("mov.b64 %0, {%1,%2};" : "=l"(u) : "f"(x), "f"(y));
    return u;
}
__device__ __forceinline__ float2 u2f(unsigned long long u) {
    float2 f;
    asm("mov.b64 {%0,%1}, %2;" : "=f"(f.x), "=f"(f.y) : "l"(u));
    return f;
}

// ---------------- split-K 64x64-tile GEMM, 128 threads, 4x8 outputs/thread -------
// partial[r][c] (pstride row stride) = X[64 x 2048 rows-major] chunk-K @ W[K x wN]
__device__ __forceinline__ void gemm_tile(const float* __restrict__ X,
                                          const float* __restrict__ W,
                                          int wN, int col0,
                                          float* __restrict__ part, int pstride,
                                          int kc0) {
    __shared__ float Xs[64][17];
    __shared__ float Ws[16][64];
    const int tid = threadIdx.x;
    const int colg = tid & 7;    // 8 col groups of 8 cols
    const int rowg = tid >> 3;   // 16 row groups of 4 rows

    unsigned long long acc[4][4];
#pragma unroll
    for (int j = 0; j < 4; j++)
#pragma unroll
        for (int p = 0; p < 4; p++) acc[j][p] = 0ull;

    for (int k0 = kc0; k0 < kc0 + KCH; k0 += 16) {
        // X tile: 64 rows x 16 k  (256 float4 loads)
#pragma unroll
        for (int j = 0; j < 2; j++) {
            int i = tid + 128 * j;
            int r = i >> 2, kq = (i & 3) * 4;
            float4 xv = *(const float4*)&X[(size_t)r * EE + k0 + kq];
            Xs[r][kq + 0] = xv.x;
            Xs[r][kq + 1] = xv.y;
            Xs[r][kq + 2] = xv.z;
            Xs[r][kq + 3] = xv.w;
        }
        // W tile: 16 k x 64 cols
#pragma unroll
        for (int j = 0; j < 2; j++) {
            int i = tid + 128 * j;
            int kk = i >> 4, cq = (i & 15) * 4;
            *(float4*)&Ws[kk][cq] =
                *(const float4*)&W[(size_t)(k0 + kk) * wN + col0 + cq];
        }
        __syncthreads();
#pragma unroll
        for (int kk = 0; kk < 16; kk++) {
            ulonglong2 wa = *(const ulonglong2*)&Ws[kk][colg * 8];
            ulonglong2 wb = *(const ulonglong2*)&Ws[kk][colg * 8 + 4];
#pragma unroll
            for (int j = 0; j < 4; j++) {
                float xv = Xs[rowg * 4 + j][kk];
                unsigned long long x2 = f2u(xv, xv);
                acc[j][0] = ffma2u(x2, wa.x, acc[j][0]);
                acc[j][1] = ffma2u(x2, wa.y, acc[j][1]);
                acc[j][2] = ffma2u(x2, wb.x, acc[j][2]);
                acc[j][3] = ffma2u(x2, wb.y, acc[j][3]);
            }
        }
        __syncthreads();
    }
#pragma unroll
    for (int j = 0; j < 4; j++) {
        float* pr = part + (size_t)(rowg * 4 + j) * pstride + colg * 8;
#pragma unroll
        for (int p = 0; p < 4; p++) *(float2*)&pr[p * 2] = u2f(acc[j][p]);
    }
}

// ---------------- kernel 1: fused QKV split-K GEMM --------------------------------
__global__ void __launch_bounds__(128) qkv_kernel(const float* __restrict__ x,
                                                  const float* __restrict__ Wq,
                                                  const float* __restrict__ Wk,
                                                  const float* __restrict__ Wv) {
    const int tile = blockIdx.x;
    const int ks = blockIdx.y;
    const int kc0 = ks * KCH;
    if (tile < 32) {
        gemm_tile(x, Wq, EE, tile * 64, &g_part[ks][0][tile * 64], 2304, kc0);
    } else if (tile < 34) {
        gemm_tile(x, Wk, DD, (tile - 32) * 64,
                  &g_part[ks][0][2048 + (tile - 32) * 64], 2304, kc0);
    } else {
        gemm_tile(x, Wv, DD, (tile - 34) * 64,
                  &g_part[ks][0][2176 + (tile - 34) * 64], 2304, kc0);
    }
}

// ---------------- kernel 1b: reduce partials + bias -------------------------------
__global__ void __launch_bounds__(256) qkv_reduce(const float* __restrict__ bq,
                                                  const float* __restrict__ bk,
                                                  const float* __restrict__ bv) {
    const int b = blockIdx.x;
    for (int i = threadIdx.x; i < 576; i += 256) {
        int c = i * 4;
        float4 s = make_float4(0.f, 0.f, 0.f, 0.f);
#pragma unroll
        for (int ks = 0; ks < KSPLIT; ks++) {
            float4 p = *(const float4*)&g_part[ks][b][c];
            s.x += p.x; s.y += p.y; s.z += p.z; s.w += p.w;
        }
        if (c < 2048) {
            float4 bb = *(const float4*)&bq[c];
            s.x += bb.x; s.y += bb.y; s.z += bb.z; s.w += bb.w;
            *(float4*)&g_q[b][c] = s;
        } else if (c < 2176) {
            float4 bb = *(const float4*)&bk[c - 2048];
            s.x += bb.x; s.y += bb.y; s.z += bb.z; s.w += bb.w;
            *(float4*)&g_kn[b][c - 2048] = s;
        } else {
            float4 bb = *(const float4*)&bv[c - 2176];
            s.x += bb.x; s.y += bb.y; s.z += bb.z; s.w += bb.w;
            *(float4*)&g_vn[b][c - 2176] = s;
        }
    }
}

// ---------------- kernel 2: flash-decode attention (pipelined tile loads) --------
__global__ void __launch_bounds__(256) attn_kernel(const float* __restrict__ kc,
                                                   const float* __restrict__ vc,
                                                   const int* __restrict__ pos) {
    const int c = blockIdx.x;  // split index
    const int b = blockIdx.y;  // batch
    const int tid = threadIdx.x;
    const int w = tid >> 5;
    const int l = tid & 31;

    __shared__ float q_s[HH][DD];       // 8 KB
    __shared__ float4 kQ[32][TILE];     // 16 KB, [dimquad][slot^dimquad]
    __shared__ float v_s[TILE][DD];     // 16 KB
    __shared__ float p_s[TILE][17];     // padded probs [slot][head]
    __shared__ float scl[HH];

    {
        const float4* qb = (const float4*)&g_q[b][0];
        ((float4*)q_s)[tid] = qb[tid];
        ((float4*)q_s)[tid + 256] = qb[tid + 256];
    }
    const int p_glob = pos[b];
    const int s0 = c * CHUNK;

    const int h0 = 2 * w;
    float m0 = -1e30f, m1 = -1e30f, l0 = 0.f, l1 = 0.f;
    const int hp = l >> 1;
    const int dbase = 16 * w + (l & 1) * 8;
    unsigned long long o[4] = {0ull, 0ull, 0ull, 0ull};
    const float scale = 0.08838834764831845f;  // 1/sqrt(128)

    const int ls = tid >> 5 << 2;  // unused placeholder removed below
    (void)ls;

    // per-thread load slots: i = tid + 256*j -> s = i>>5 (0..31), dq = i&31
    float4 kr[4], vr[4];
#pragma unroll
    for (int j = 0; j < 4; j++) {
        int i = tid + 256 * j;
        int s = i >> 5, dq = i & 31;
        size_t g = ((size_t)b * S_TOT + s0 + s) * DD + dq * 4;
        kr[j] = *(const float4*)&kc[g];
        vr[j] = *(const float4*)&vc[g];
    }

    for (int t = 0; t < CHUNK / TILE; t++) {
        const int sbase = s0 + t * TILE;
        __syncthreads();  // previous tile fully consumed; q_s ready (iter 0)

        // store prefetched tile into smem (K transposed + xor-swizzled)
#pragma unroll
        for (int j = 0; j < 4; j++) {
            int i = tid + 256 * j;
            int s = i >> 5, dq = i & 31;
            kQ[dq][s ^ dq] = kr[j];
            *(float4*)&v_s[s][dq * 4] = vr[j];
        }
        // prefetch next tile (global latency overlapped with compute below)
        if (t + 1 < CHUNK / TILE) {
#pragma unroll
            for (int j = 0; j < 4; j++) {
                int i = tid + 256 * j;
                int s = i >> 5, dq = i & 31;
                size_t g = ((size_t)b * S_TOT + sbase + TILE + s) * DD + dq * 4;
                kr[j] = *(const float4*)&kc[g];
                vr[j] = *(const float4*)&vc[g];
            }
        }
        const bool fix = (p_glob >= sbase) && (p_glob < sbase + TILE);
        __syncthreads();
        if (fix) {
            if (tid < 32) {
                int pl = p_glob - sbase;
                kQ[tid][pl ^ tid] = *(const float4*)&g_kn[b][tid * 4];
                *(float4*)&v_s[pl][tid * 4] = *(const float4*)&g_vn[b][tid * 4];
            }
            __syncthreads();
        }

        // ---- QK: lane = slot, 2 heads per warp ----
        unsigned long long a0 = 0ull, a1 = 0ull;
#pragma unroll
        for (int dq = 0; dq < 32; dq++) {
            ulonglong2 kv = *(const ulonglong2*)&kQ[dq][l ^ dq];
            ulonglong2 q0 = *(const ulonglong2*)&q_s[h0][dq * 4];
            ulonglong2 q1 = *(const ulonglong2*)&q_s[h0 + 1][dq * 4];
            a0 = ffma2u(kv.x, q0.x, a0);
            a0 = ffma2u(kv.y, q0.y, a0);
            a1 = ffma2u(kv.x, q1.x, a1);
            a1 = ffma2u(kv.y, q1.y, a1);
        }
        float2 f0 = u2f(a0), f1 = u2f(a1);
        float sc0 = (f0.x + f0.y) * scale;
        float sc1 = (f1.x + f1.y) * scale;

        float t0 = sc0, t1 = sc1;
#pragma unroll
        for (int off = 16; off; off >>= 1) {
            t0 = fmaxf(t0, __shfl_xor_sync(0xffffffffu, t0, off));
            t1 = fmaxf(t1, __shfl_xor_sync(0xffffffffu, t1, off));
        }
        float nm0 = fmaxf(m0, t0), nm1 = fmaxf(m1, t1);
        float cr0 = __expf(m0 - nm0), cr1 = __expf(m1 - nm1);
        float p0 = __expf(sc0 - nm0), p1 = __expf(sc1 - nm1);
        float ps0 = p0, ps1 = p1;
#pragma unroll
        for (int off = 16; off; off >>= 1) {
            ps0 += __shfl_xor_sync(0xffffffffu, ps0, off);
            ps1 += __shfl_xor_sync(0xffffffffu, ps1, off);
        }
        l0 = l0 * cr0 + ps0;
        l1 = l1 * cr1 + ps1;
        m0 = nm0;
        m1 = nm1;
        p_s[l][h0] = p0;
        p_s[l][h0 + 1] = p1;
        if (l == 0) {
            scl[h0] = cr0;
            scl[h0 + 1] = cr1;
        }
        __syncthreads();

        // ---- PV: warp owns 16 dims for all heads ----
        {
            float cr = scl[hp];
            unsigned long long cr2 = f2u(cr, cr);
#pragma unroll
            for (int j = 0; j < 4; j++) o[j] = fmul2u(o[j], cr2);
        }
#pragma unroll
        for (int s = 0; s < TILE; s++) {
            float p = p_s[s][hp];
            unsigned long long p2 = f2u(p, p);
            ulonglong2 va = *(const ulonglong2*)&v_s[s][dbase];
            ulonglong2 vb = *(const ulonglong2*)&v_s[s][dbase + 4];
            o[0] = ffma2u(va.x, p2, o[0]);
            o[1] = ffma2u(va.y, p2, o[1]);
            o[2] = ffma2u(vb.x, p2, o[2]);
            o[3] = ffma2u(vb.y, p2, o[3]);
        }
    }
    __syncthreads();

    if (l == 0) {
        g_pm[b][c][h0] = m0;
        g_pl[b][c][h0] = l0;
        g_pm[b][c][h0 + 1] = m1;
        g_pl[b][c][h0 + 1] = l1;
    }
    {
        float* op = &g_po[b][c][hp][dbase];
        float2 f;
        f = u2f(o[0]); op[0] = f.x; op[1] = f.y;
        f = u2f(o[1]); op[2] = f.x; op[3] = f.y;
        f = u2f(o[2]); op[4] = f.x; op[5] = f.y;
        f = u2f(o[3]); op[6] = f.x; op[7] = f.y;
    }
}

// ---------------- kernel 3: combine split partials -------------------------------
__global__ void __launch_bounds__(256) combine_kernel() {
    const int b = blockIdx.x;
    const int tid = threadIdx.x;
    __shared__ float wgt[HH][NSPLIT];
    if (tid < HH) {
        float M = -1e30f;
#pragma unroll
        for (int cc = 0; cc < NSPLIT; cc++) M = fmaxf(M, g_pm[b][cc][tid]);
        float den = 0.f;
        float e[NSPLIT];
#pragma unroll
        for (int cc = 0; cc < NSPLIT; cc++) {
            e[cc] = __expf(g_pm[b][cc][tid] - M);
            den += e[cc] * g_pl[b][cc][tid];
        }
        float inv = 1.f / den;
#pragma unroll
        for (int cc = 0; cc < NSPLIT; cc++) wgt[tid][cc] = e[cc] * inv;
    }
    __syncthreads();
    for (int i = tid; i < EE; i += 256) {
        int h = i >> 7, d = i & 127;
        float acc = 0.f;
#pragma unroll
        for (int cc = 0; cc < NSPLIT; cc++) acc += wgt[h][cc] * g_po[b][cc][h][d];
        g_attn[b][i] = acc;
    }
}

// ---------------- kernel 4: output projection split-K GEMM ------------------------
__global__ void __launch_bounds__(128) oproj_kernel(const float* __restrict__ Wo) {
    const int tile = blockIdx.x;
    const int ks = blockIdx.y;
    gemm_tile(&g_attn[0][0], Wo, EE, tile * 64, &g_part2[ks][0][tile * 64], EE,
              ks * KCH);
}

__global__ void __launch_bounds__(256) oproj_reduce(const float* __restrict__ bo,
                                                    float* __restrict__ out) {
    const int b = blockIdx.x;
    for (int i = threadIdx.x; i < 512; i += 256) {
        int cq = i * 4;
        float4 s = make_float4(0.f, 0.f, 0.f, 0.f);
#pragma unroll
        for (int ks = 0; ks < KSPLIT; ks++) {
            float4 p = *(const float4*)&g_part2[ks][b][cq];
            s.x += p.x; s.y += p.y; s.z += p.z; s.w += p.w;
        }
        float4 bb = *(const float4*)&bo[cq];
        s.x += bb.x; s.y += bb.y; s.z += bb.z; s.w += bb.w;
        *(float4*)&out[(size_t)b * EE + cq] = s;
    }
}

// ---------------- launch ----------------------------------------------------------
extern "C" void kernel_launch(void* const* d_in, const int* in_sizes, int n_in,
                              void* d_out, int out_size) {
    const float* x  = (const float*)d_in[0];
    const float* kc = (const float*)d_in[1];
    const float* vc = (const float*)d_in[2];
    const int* pos  = (const int*)d_in[3];
    const float* Wq = (const float*)d_in[4];
    const float* bq = (const float*)d_in[5];
    const float* Wk = (const float*)d_in[6];
    const float* bk = (const float*)d_in[7];
    const float* Wv = (const float*)d_in[8];
    const float* bv = (const float*)d_in[9];
    const float* Wo = (const float*)d_in[10];
    const float* bo = (const float*)d_in[11];
    float* out = (float*)d_out;

    qkv_kernel<<<dim3(36, KSPLIT), 128>>>(x, Wq, Wk, Wv);
    qkv_reduce<<<BB, 256>>>(bq, bk, bv);
    attn_kernel<<<dim3(NSPLIT, BB), 256>>>(kc, vc, pos);
    combine_kernel<<<BB, 256>>>();
    oproj_kernel<<<dim3(32, KSPLIT), 128>>>(Wo);
    oproj_reduce<<<BB, 256>>>(bo, out);
}